// round 4
// baseline (speedup 1.0000x reference)
#include <cuda_runtime.h>
#include <cuda_bf16.h>
#include <math.h>

// Problem constants
#define Sq    2048
#define HIDN  2048
#define NH    16
#define NKH   8
#define HD    128
#define GRP   2          // NH / NKH
#define EPSV  1e-6f
#define SCALEV 0.08838834764831845f   // 128^-0.5

// ---------------- static device scratch (allocation-free rule) ----------------
__device__ float g_q[Sq * NH * HD];               // 2048 x 2048
__device__ float g_k[Sq * NKH * HD];              // 2048 x 1024
__device__ float g_v[Sq * NKH * HD];              // 2048 x 1024
__device__ float g_y[Sq * NH * HD];               // 2048 x 2048

// ---------------- tf32 helpers ----------------
__device__ __forceinline__ unsigned f2tf32(float f) {
    unsigned u;
    asm("cvt.rna.tf32.f32 %0, %1;" : "=r"(u) : "f"(f));
    return u;
}

__device__ __forceinline__ void mma_tf32(float c[4],
                                         unsigned a0, unsigned a1, unsigned a2, unsigned a3,
                                         unsigned b0, unsigned b1)
{
    asm volatile(
        "mma.sync.aligned.m16n8k8.row.col.f32.tf32.tf32.f32 "
        "{%0,%1,%2,%3}, {%4,%5,%6,%7}, {%8,%9}, {%0,%1,%2,%3};"
        : "+f"(c[0]), "+f"(c[1]), "+f"(c[2]), "+f"(c[3])
        : "r"(a0), "r"(a1), "r"(a2), "r"(a3), "r"(b0), "r"(b1));
}

// ---------------- double-buffered tf32 GEMM: C = A @ B^T ----------------
// A: M x K row-major (lda), B: N x K row-major (ldb), C: M x N (ldc).
// Block tile 128x128, k-tile 32, 8 warps (warp = 32x64), 2-stage smem pipeline.
#define GP 136                       // padded k-slice stride
#define GEMM_SMEM (4 * 32 * GP * 4)  // 2 stages x (A+B) x 32 x 136 x 4B = 69632

__global__ __launch_bounds__(256, 1)
void mma_gemm(const float* __restrict__ A,
              const float* __restrict__ B,
              float* __restrict__ C,
              int M, int N, int K,
              int lda, int ldb, int ldc)
{
    extern __shared__ unsigned dsm[];
    unsigned* Abuf[2] = { dsm,               dsm + 2 * 32 * GP };
    unsigned* Bbuf[2] = { dsm + 32 * GP,     dsm + 3 * 32 * GP };

    const int bm = blockIdx.y * 128;
    const int bn = blockIdx.x * 128;

    const int tid  = threadIdx.x;       // 256 threads = 8 warps
    const int lane = tid & 31;
    const int wid  = tid >> 5;
    const int wm   = wid & 3;           // 4 x 32 rows
    const int wn   = wid >> 2;          // 2 x 64 cols
    const int gid  = lane >> 2;
    const int tig  = lane & 3;

    const int lrow = tid >> 3;          // 0..31? no: 0..127? tid>>3 max 31 -> need f
    // per-thread load coords (4 chunks of 256 threads cover 128 rows x 8 float4)
    // f = tid + i*256 ; row = f>>3 (0..127) ; c4 = f&7

    float acc[2][8][4];
    #pragma unroll
    for (int mt = 0; mt < 2; mt++)
        #pragma unroll
        for (int nt = 0; nt < 8; nt++)
            #pragma unroll
            for (int r = 0; r < 4; r++)
                acc[mt][nt][r] = 0.0f;

    float4 ra[4], rb[4];

    // ---- prologue: load k-tile 0 into regs, store to stage 0 ----
    #pragma unroll
    for (int i = 0; i < 4; i++) {
        int f = tid + i * 256;
        int row = f >> 3, c4 = f & 7;
        ra[i] = *(const float4*)&A[(size_t)(bm + row) * lda + c4 * 4];
        rb[i] = *(const float4*)&B[(size_t)(bn + row) * ldb + c4 * 4];
    }
    #pragma unroll
    for (int i = 0; i < 4; i++) {
        int f = tid + i * 256;
        int row = f >> 3, c4 = f & 7;
        Abuf[0][(c4 * 4 + 0) * GP + row] = f2tf32(ra[i].x);
        Abuf[0][(c4 * 4 + 1) * GP + row] = f2tf32(ra[i].y);
        Abuf[0][(c4 * 4 + 2) * GP + row] = f2tf32(ra[i].z);
        Abuf[0][(c4 * 4 + 3) * GP + row] = f2tf32(ra[i].w);
        Bbuf[0][(c4 * 4 + 0) * GP + row] = f2tf32(rb[i].x);
        Bbuf[0][(c4 * 4 + 1) * GP + row] = f2tf32(rb[i].y);
        Bbuf[0][(c4 * 4 + 2) * GP + row] = f2tf32(rb[i].z);
        Bbuf[0][(c4 * 4 + 3) * GP + row] = f2tf32(rb[i].w);
    }
    __syncthreads();

    int cur = 0;
    for (int k0 = 0; k0 < K; k0 += 32) {
        const bool has_next = (k0 + 32) < K;

        // ---- prefetch next tile into registers (LDGs in flight over compute) ----
        if (has_next) {
            #pragma unroll
            for (int i = 0; i < 4; i++) {
                int f = tid + i * 256;
                int row = f >> 3, c4 = f & 7;
                ra[i] = *(const float4*)&A[(size_t)(bm + row) * lda + (k0 + 32) + c4 * 4];
                rb[i] = *(const float4*)&B[(size_t)(bn + row) * ldb + (k0 + 32) + c4 * 4];
            }
        }

        // ---- compute on current stage ----
        unsigned* As = Abuf[cur];
        unsigned* Bs = Bbuf[cur];
        #pragma unroll
        for (int ks = 0; ks < 32; ks += 8) {
            unsigned a[2][4];
            #pragma unroll
            for (int mt = 0; mt < 2; mt++) {
                int mrow = wm * 32 + mt * 16;
                a[mt][0] = As[(ks + tig    ) * GP + mrow + gid];
                a[mt][1] = As[(ks + tig    ) * GP + mrow + gid + 8];
                a[mt][2] = As[(ks + tig + 4) * GP + mrow + gid];
                a[mt][3] = As[(ks + tig + 4) * GP + mrow + gid + 8];
            }
            unsigned b[8][2];
            #pragma unroll
            for (int nt = 0; nt < 8; nt++) {
                int ncol = wn * 64 + nt * 8;
                b[nt][0] = Bs[(ks + tig    ) * GP + ncol + gid];
                b[nt][1] = Bs[(ks + tig + 4) * GP + ncol + gid];
            }
            #pragma unroll
            for (int mt = 0; mt < 2; mt++)
                #pragma unroll
                for (int nt = 0; nt < 8; nt++)
                    mma_tf32(acc[mt][nt],
                             a[mt][0], a[mt][1], a[mt][2], a[mt][3],
                             b[nt][0], b[nt][1]);
        }

        // ---- store prefetched tile to the other stage ----
        if (has_next) {
            unsigned* An = Abuf[cur ^ 1];
            unsigned* Bn = Bbuf[cur ^ 1];
            #pragma unroll
            for (int i = 0; i < 4; i++) {
                int f = tid + i * 256;
                int row = f >> 3, c4 = f & 7;
                An[(c4 * 4 + 0) * GP + row] = f2tf32(ra[i].x);
                An[(c4 * 4 + 1) * GP + row] = f2tf32(ra[i].y);
                An[(c4 * 4 + 2) * GP + row] = f2tf32(ra[i].z);
                An[(c4 * 4 + 3) * GP + row] = f2tf32(ra[i].w);
                Bn[(c4 * 4 + 0) * GP + row] = f2tf32(rb[i].x);
                Bn[(c4 * 4 + 1) * GP + row] = f2tf32(rb[i].y);
                Bn[(c4 * 4 + 2) * GP + row] = f2tf32(rb[i].z);
                Bn[(c4 * 4 + 3) * GP + row] = f2tf32(rb[i].w);
            }
            __syncthreads();
            cur ^= 1;
        }
    }

    // ---- epilogue ----
    #pragma unroll
    for (int mt = 0; mt < 2; mt++) {
        #pragma unroll
        for (int nt = 0; nt < 8; nt++) {
            int r0 = bm + wm * 32 + mt * 16 + gid;
            int c0 = bn + wn * 64 + nt * 8 + tig * 2;
            *(float2*)&C[(size_t)r0       * ldc + c0] = make_float2(acc[mt][nt][0], acc[mt][nt][1]);
            *(float2*)&C[(size_t)(r0 + 8) * ldc + c0] = make_float2(acc[mt][nt][2], acc[mt][nt][3]);
        }
    }
}

// ---------------- fused flash attention (tf32 mma, online softmax) ----------------
#define QS_PAD 132
#define KS_PAD 132
#define VS_PAD 136
#define SM_QS  0
#define SM_KS  (128 * QS_PAD)
#define SM_VS  (SM_KS + 64 * KS_PAD)
#define SM_TOT ((SM_VS + 64 * VS_PAD) * 4)   // bytes = 136192

__global__ __launch_bounds__(256, 1)
void flash_kernel(const float* __restrict__ q,
                  const float* __restrict__ k,
                  const float* __restrict__ v,
                  float* __restrict__ y)
{
    extern __shared__ unsigned sm[];
    unsigned* Qs = sm + SM_QS;
    unsigned* Ks = sm + SM_KS;
    unsigned* Vs = sm + SM_VS;

    const int head = blockIdx.x;
    const int kh   = head / GRP;
    const int bq   = (gridDim.y - 1) - blockIdx.y;   // heavy blocks first

    const int tid  = threadIdx.x;
    const int lane = tid & 31;
    const int wid  = tid >> 5;
    const int gid  = lane >> 2;
    const int tig  = lane & 3;

    // ---- load Q tile (128 x 128) ----
    #pragma unroll
    for (int i = 0; i < 16; i++) {
        int f   = tid + i * 256;
        int row = f >> 5;
        int c4  = f & 31;
        float4 t = *(const float4*)&q[(size_t)(bq * 128 + row) * (NH * HD) + head * HD + c4 * 4];
        *(uint4*)&Qs[row * QS_PAD + c4 * 4] =
            make_uint4(f2tf32(t.x), f2tf32(t.y), f2tf32(t.z), f2tf32(t.w));
    }

    float Oa[16][4];
    #pragma unroll
    for (int nt = 0; nt < 16; nt++)
        #pragma unroll
        for (int r = 0; r < 4; r++)
            Oa[nt][r] = 0.0f;
    float mrow0 = -1e30f, mrow1 = -1e30f;
    float lrow0 = 0.0f,   lrow1 = 0.0f;

    const int i0 = bq * 128 + wid * 16 + gid;
    const int nkb = 2 * (bq + 1);

    for (int kb = 0; kb < nkb; kb++) {
        const int k0 = kb * 64;

        __syncthreads();
        #pragma unroll
        for (int i = 0; i < 8; i++) {
            int f   = tid + i * 256;
            int key = f >> 5;
            int c4  = f & 31;
            size_t goff = (size_t)(k0 + key) * (NKH * HD) + kh * HD + c4 * 4;
            float4 tk = *(const float4*)&k[goff];
            *(uint4*)&Ks[key * KS_PAD + c4 * 4] =
                make_uint4(f2tf32(tk.x), f2tf32(tk.y), f2tf32(tk.z), f2tf32(tk.w));
            float4 tv = *(const float4*)&v[goff];
            *(uint4*)&Vs[key * VS_PAD + c4 * 4] =
                make_uint4(f2tf32(tv.x), f2tf32(tv.y), f2tf32(tv.z), f2tf32(tv.w));
        }
        __syncthreads();

        // ---- S = Q @ K^T ----
        float s[8][4];
        #pragma unroll
        for (int nt = 0; nt < 8; nt++)
            #pragma unroll
            for (int r = 0; r < 4; r++)
                s[nt][r] = 0.0f;

        #pragma unroll
        for (int ks = 0; ks < 128; ks += 8) {
            unsigned a0 = Qs[(wid * 16 + gid    ) * QS_PAD + ks + tig];
            unsigned a1 = Qs[(wid * 16 + gid + 8) * QS_PAD + ks + tig];
            unsigned a2 = Qs[(wid * 16 + gid    ) * QS_PAD + ks + tig + 4];
            unsigned a3 = Qs[(wid * 16 + gid + 8) * QS_PAD + ks + tig + 4];
            #pragma unroll
            for (int nt = 0; nt < 8; nt++) {
                unsigned b0 = Ks[(nt * 8 + gid) * KS_PAD + ks + tig];
                unsigned b1 = Ks[(nt * 8 + gid) * KS_PAD + ks + tig + 4];
                mma_tf32(s[nt], a0, a1, a2, a3, b0, b1);
            }
        }

        // ---- scale + causal mask ----
        const bool diag = (k0 + 64 > bq * 128);
        #pragma unroll
        for (int nt = 0; nt < 8; nt++) {
            int j = k0 + nt * 8 + tig * 2;
            #pragma unroll
            for (int r = 0; r < 4; r++) {
                int jj = j + (r & 1);
                int ii = i0 + ((r >> 1) << 3);
                float val = s[nt][r] * SCALEV;
                if (diag && jj > ii) val = -1e30f;
                s[nt][r] = val;
            }
        }

        // ---- online softmax ----
        float mx0 = -1e30f, mx1 = -1e30f;
        #pragma unroll
        for (int nt = 0; nt < 8; nt++) {
            mx0 = fmaxf(mx0, fmaxf(s[nt][0], s[nt][1]));
            mx1 = fmaxf(mx1, fmaxf(s[nt][2], s[nt][3]));
        }
        mx0 = fmaxf(mx0, __shfl_xor_sync(0xffffffffu, mx0, 1));
        mx0 = fmaxf(mx0, __shfl_xor_sync(0xffffffffu, mx0, 2));
        mx1 = fmaxf(mx1, __shfl_xor_sync(0xffffffffu, mx1, 1));
        mx1 = fmaxf(mx1, __shfl_xor_sync(0xffffffffu, mx1, 2));

        float mnew0 = fmaxf(mrow0, mx0);
        float mnew1 = fmaxf(mrow1, mx1);
        float corr0 = __expf(mrow0 - mnew0);
        float corr1 = __expf(mrow1 - mnew1);
        mrow0 = mnew0; mrow1 = mnew1;

        float sum0 = 0.0f, sum1 = 0.0f;
        #pragma unroll
        for (int nt = 0; nt < 8; nt++) {
            s[nt][0] = __expf(s[nt][0] - mnew0);
            s[nt][1] = __expf(s[nt][1] - mnew0);
            s[nt][2] = __expf(s[nt][2] - mnew1);
            s[nt][3] = __expf(s[nt][3] - mnew1);
            sum0 += s[nt][0] + s[nt][1];
            sum1 += s[nt][2] + s[nt][3];
        }
        sum0 += __shfl_xor_sync(0xffffffffu, sum0, 1);
        sum0 += __shfl_xor_sync(0xffffffffu, sum0, 2);
        sum1 += __shfl_xor_sync(0xffffffffu, sum1, 1);
        sum1 += __shfl_xor_sync(0xffffffffu, sum1, 2);
        lrow0 = lrow0 * corr0 + sum0;
        lrow1 = lrow1 * corr1 + sum1;

        #pragma unroll
        for (int nt = 0; nt < 16; nt++) {
            Oa[nt][0] *= corr0;  Oa[nt][1] *= corr0;
            Oa[nt][2] *= corr1;  Oa[nt][3] *= corr1;
        }

        // ---- O += P @ V ----
        const int srcA = (lane & ~3) | (tig >> 1);
        const int srcB = srcA + 2;
        const bool odd = (tig & 1);
        #pragma unroll
        for (int ks8 = 0; ks8 < 8; ks8++) {
            unsigned p0 = f2tf32(s[ks8][0]);
            unsigned p1 = f2tf32(s[ks8][1]);
            unsigned p2 = f2tf32(s[ks8][2]);
            unsigned p3 = f2tf32(s[ks8][3]);
            unsigned x0 = __shfl_sync(0xffffffffu, p0, srcA);
            unsigned x1 = __shfl_sync(0xffffffffu, p1, srcA);
            unsigned x2 = __shfl_sync(0xffffffffu, p2, srcA);
            unsigned x3 = __shfl_sync(0xffffffffu, p3, srcA);
            unsigned y0 = __shfl_sync(0xffffffffu, p0, srcB);
            unsigned y1 = __shfl_sync(0xffffffffu, p1, srcB);
            unsigned y2 = __shfl_sync(0xffffffffu, p2, srcB);
            unsigned y3 = __shfl_sync(0xffffffffu, p3, srcB);
            unsigned a0 = odd ? x1 : x0;
            unsigned a1 = odd ? x3 : x2;
            unsigned a2 = odd ? y1 : y0;
            unsigned a3 = odd ? y3 : y2;
            #pragma unroll
            for (int nt = 0; nt < 16; nt++) {
                unsigned b0 = Vs[(ks8 * 8 + tig    ) * VS_PAD + nt * 8 + gid];
                unsigned b1 = Vs[(ks8 * 8 + tig + 4) * VS_PAD + nt * 8 + gid];
                mma_tf32(Oa[nt], a0, a1, a2, a3, b0, b1);
            }
        }
    }

    // ---- finalize & store ----
    float inv0 = 1.0f / lrow0;
    float inv1 = 1.0f / lrow1;
    #pragma unroll
    for (int nt = 0; nt < 16; nt++) {
        int c0 = head * HD + nt * 8 + tig * 2;
        *(float2*)&y[(size_t)i0       * (NH * HD) + c0] = make_float2(Oa[nt][0] * inv0, Oa[nt][1] * inv0);
        *(float2*)&y[(size_t)(i0 + 8) * (NH * HD) + c0] = make_float2(Oa[nt][2] * inv1, Oa[nt][3] * inv1);
    }
}

// ---------------- RMSNorm + RoPE: one warp per (s, h) row ----------------
// block = 128 (4 warps = 4 rows), grid = Sq*nh/4
__global__ __launch_bounds__(128)
void norm_rope_kernel(float* __restrict__ x,
                      const float* __restrict__ w,
                      const float* __restrict__ pcos,
                      const float* __restrict__ psin,
                      int nh)
{
    const int idx  = blockIdx.x * 4 + (threadIdx.x >> 5);  // row over s*nh
    const int lane = threadIdx.x & 31;
    const int s    = idx / nh;

    float* row = x + (size_t)idx * HD;
    float4 val = *(float4*)&row[lane * 4];

    float ssq = val.x * val.x + val.y * val.y + val.z * val.z + val.w * val.w;
    #pragma unroll
    for (int off = 16; off > 0; off >>= 1)
        ssq += __shfl_xor_sync(0xffffffffu, ssq, off);

    float r = rsqrtf(ssq * (1.0f / HD) + EPSV);
    float4 wv = *(const float4*)&w[lane * 4];
    float4 xn = make_float4(val.x * r * wv.x, val.y * r * wv.y,
                            val.z * r * wv.z, val.w * r * wv.w);

    // partner values (d xor 64 <-> lane xor 16)
    float px = __shfl_xor_sync(0xffffffffu, xn.x, 16);
    float py = __shfl_xor_sync(0xffffffffu, xn.y, 16);
    float pz = __shfl_xor_sync(0xffffffffu, xn.z, 16);
    float pw = __shfl_xor_sync(0xffffffffu, xn.w, 16);

    const int cidx = (lane & 15) * 4;
    float4 cv = *(const float4*)&pcos[s * 64 + cidx];
    float4 sv = *(const float4*)&psin[s * 64 + cidx];

    float4 o;
    if (lane < 16) {  // real part: xr*c - xi*s
        o = make_float4(xn.x * cv.x - px * sv.x, xn.y * cv.y - py * sv.y,
                        xn.z * cv.z - pz * sv.z, xn.w * cv.w - pw * sv.w);
    } else {          // imag part: xr*s + xi*c
        o = make_float4(px * sv.x + xn.x * cv.x, py * sv.y + xn.y * cv.y,
                        pz * sv.z + xn.z * cv.z, pw * sv.w + xn.w * cv.w);
    }
    *(float4*)&row[lane * 4] = o;
}

// ---------------- k_new / v_new tail copy ----------------
__global__ void tail_copy_kernel(const float* __restrict__ k,
                                 const float* __restrict__ v,
                                 float* __restrict__ out)
{
    int t = blockIdx.x * blockDim.x + threadIdx.x;   // 0..2047
    const size_t base = (size_t)Sq * HIDN;           // after y
    if (t < NKH * HD)
        out[base + t] = k[(size_t)(Sq - 1) * (NKH * HD) + t];
    else
        out[base + t] = v[(size_t)(Sq - 1) * (NKH * HD) + (t - NKH * HD)];
}

// ---------------- launcher ----------------
extern "C" void kernel_launch(void* const* d_in, const int* in_sizes, int n_in,
                              void* d_out, int out_size)
{
    const float* hs   = (const float*)d_in[0];
    const float* pcos = (const float*)d_in[1];
    const float* psin = (const float*)d_in[2];
    // d_in[3] = atten_mask (causal, reproduced arithmetically)
    const float* Wq   = (const float*)d_in[4];
    const float* Wk   = (const float*)d_in[5];
    const float* Wv   = (const float*)d_in[6];
    const float* Wo   = (const float*)d_in[7];
    const float* qw   = (const float*)d_in[8];
    const float* kw   = (const float*)d_in[9];
    float* out = (float*)d_out;

    float *q, *k, *v, *y;
    cudaGetSymbolAddress((void**)&q, g_q);
    cudaGetSymbolAddress((void**)&k, g_k);
    cudaGetSymbolAddress((void**)&v, g_v);
    cudaGetSymbolAddress((void**)&y, g_y);

    cudaFuncSetAttribute(mma_gemm,
                         cudaFuncAttributeMaxDynamicSharedMemorySize, GEMM_SMEM);
    cudaFuncSetAttribute(flash_kernel,
                         cudaFuncAttributeMaxDynamicSharedMemorySize, SM_TOT);

    dim3 blk(256);

    // ---- QKV projections: X(2048x2048) @ W^T ----
    mma_gemm<<<dim3(16, 16), blk, GEMM_SMEM>>>(hs, Wq, q, Sq, NH * HD,  HIDN, HIDN, HIDN, NH * HD);
    mma_gemm<<<dim3(8,  16), blk, GEMM_SMEM>>>(hs, Wk, k, Sq, NKH * HD, HIDN, HIDN, HIDN, NKH * HD);
    mma_gemm<<<dim3(8,  16), blk, GEMM_SMEM>>>(hs, Wv, v, Sq, NKH * HD, HIDN, HIDN, HIDN, NKH * HD);

    // ---- RMSNorm + RoPE ----
    norm_rope_kernel<<<Sq * NH  / 4, 128>>>(q, qw, pcos, psin, NH);
    norm_rope_kernel<<<Sq * NKH / 4, 128>>>(k, kw, pcos, psin, NKH);

    // ---- fused attention (scores + softmax + AV) ----
    flash_kernel<<<dim3(NH, Sq / 128), blk, SM_TOT>>>(q, k, v, y);

    // ---- output projection: Y(2048x2048) @ Wo^T ----
    mma_gemm<<<dim3(16, 16), blk, GEMM_SMEM>>>(y, Wo, out, Sq, HIDN, HIDN, NH * HD, HIDN, HIDN);

    // ---- k_new / v_new ----
    tail_copy_kernel<<<8, 256>>>(k, v, out);
}

// round 5
// speedup vs baseline: 1.8450x; 1.8450x over previous
#include <cuda_runtime.h>
#include <cuda_bf16.h>
#include <math.h>

// Problem constants
#define Sq    2048
#define HIDN  2048
#define NH    16
#define NKH   8
#define HD    128
#define GRP   2          // NH / NKH
#define EPSV  1e-6f
#define SCALEV 0.08838834764831845f   // 128^-0.5

#define NQ (NH * HD)     // 2048
#define NKV (NKH * HD)   // 1024
#define NQKV (NQ + 2 * NKV)  // 4096

// ---------------- static device scratch (allocation-free rule) ----------------
__device__ float g_q[Sq * NQ];
__device__ float g_k[Sq * NKV];
__device__ float g_v[Sq * NKV];
__device__ float g_y[Sq * NQ];
__device__ unsigned g_hsT[HIDN * Sq];        // tf32, [k][m]
__device__ unsigned g_wqkvT[HIDN * NQKV];    // tf32, [k][n]  (Wq|Wk|Wv)
__device__ unsigned g_woT[NQ * HIDN];        // tf32, [k][n]
__device__ unsigned g_yT[NQ * Sq];           // tf32, [k][m]

// ---------------- tf32 helpers ----------------
__device__ __forceinline__ unsigned f2tf32(float f) {
    unsigned u;
    asm("cvt.rna.tf32.f32 %0, %1;" : "=r"(u) : "f"(f));
    return u;
}

__device__ __forceinline__ void mma_tf32(float c[4],
                                         unsigned a0, unsigned a1, unsigned a2, unsigned a3,
                                         unsigned b0, unsigned b1)
{
    asm volatile(
        "mma.sync.aligned.m16n8k8.row.col.f32.tf32.tf32.f32 "
        "{%0,%1,%2,%3}, {%4,%5,%6,%7}, {%8,%9}, {%0,%1,%2,%3};"
        : "+f"(c[0]), "+f"(c[1]), "+f"(c[2]), "+f"(c[3])
        : "r"(a0), "r"(a1), "r"(a2), "r"(a3), "r"(b0), "r"(b1));
}

__device__ __forceinline__ void cpa16(unsigned dst, const unsigned* src) {
    asm volatile("cp.async.cg.shared.global [%0], [%1], 16;\n" :: "r"(dst), "l"(src));
}
#define CP_COMMIT() asm volatile("cp.async.commit_group;\n")
#define CP_WAIT2()  asm volatile("cp.async.wait_group 2;\n")

// ---------------- transpose + tf32 convert ----------------
// in: R x C fp32 row-major (ldin = C). out[c][coloff + r] = tf32(in[r][c]), row stride ldout.
__global__ __launch_bounds__(256)
void transpose_tf32_kernel(const float* __restrict__ in, unsigned* __restrict__ out,
                           int ldin, int ldout, int coloff)
{
    __shared__ float t[32][33];
    const int c0 = blockIdx.x * 32;
    const int r0 = blockIdx.y * 32;
    const int tx = threadIdx.x & 31;
    const int ty = threadIdx.x >> 5;   // 0..7

    #pragma unroll
    for (int i = 0; i < 32; i += 8)
        t[ty + i][tx] = in[(size_t)(r0 + ty + i) * ldin + c0 + tx];
    __syncthreads();
    #pragma unroll
    for (int i = 0; i < 32; i += 8)
        out[(size_t)(c0 + ty + i) * ldout + coloff + r0 + tx] = f2tf32(t[tx][ty + i]);
}

// ---------------- cp.async 3-stage pipelined tf32 GEMM ----------------
// At: K x M tf32 k-major (ldA), Bt: K x N tf32 k-major (ldB).
// C[m][n] += ... fp32. Block tile 128x128, k-tile 32, 8 warps (32x64 each).
// QKV mode: N=4096 concatenated -> route block to q/k/v by bn.
#define GP 136
#define STG_WORDS (2 * 32 * GP)              // A+B per stage = 8704 words
#define NSTAGE 3
#define GEMM_SMEM (NSTAGE * STG_WORDS * 4)   // 104448 bytes

__device__ __forceinline__ void gemm_issue(unsigned smA, unsigned smB,
                                           const unsigned* At, const unsigned* Bt,
                                           int ldA, int ldB, int kt,
                                           int bm, int bn, int tid)
{
    #pragma unroll
    for (int i = 0; i < 4; i++) {
        int e  = tid + i * 256;
        int kk = e >> 5;       // 0..31
        int mc = e & 31;       // 0..31 (x4 elems)
        cpa16(smA + (unsigned)(kk * GP + mc * 4) * 4,
              At + (size_t)(kt * 32 + kk) * ldA + bm + mc * 4);
        cpa16(smB + (unsigned)(kk * GP + mc * 4) * 4,
              Bt + (size_t)(kt * 32 + kk) * ldB + bn + mc * 4);
    }
}

template <bool QKV>
__global__ __launch_bounds__(256, 2)
void mma_gemm(const unsigned* __restrict__ At, const unsigned* __restrict__ Bt,
              float* __restrict__ C0, float* __restrict__ C1, float* __restrict__ C2,
              int ldA, int ldB, int K, int ldc_plain)
{
    extern __shared__ unsigned sm[];
    const unsigned smbase = (unsigned)__cvta_generic_to_shared(sm);

    const int bm = blockIdx.y * 128;
    const int bn = blockIdx.x * 128;

    const int tid  = threadIdx.x;
    const int lane = tid & 31;
    const int wid  = tid >> 5;
    const int wm   = wid & 3;
    const int wn   = wid >> 2;
    const int gid  = lane >> 2;
    const int tig  = lane & 3;

    float acc[2][8][4];
    #pragma unroll
    for (int mt = 0; mt < 2; mt++)
        #pragma unroll
        for (int nt = 0; nt < 8; nt++)
            #pragma unroll
            for (int r = 0; r < 4; r++)
                acc[mt][nt][r] = 0.0f;

    const int NT = K / 32;

    // prologue: stages 0,1
    gemm_issue(smbase, smbase + 32 * GP * 4, At, Bt, ldA, ldB, 0, bm, bn, tid);
    CP_COMMIT();
    gemm_issue(smbase + STG_WORDS * 4, smbase + (STG_WORDS + 32 * GP) * 4,
               At, Bt, ldA, ldB, 1, bm, bn, tid);
    CP_COMMIT();

    for (int kt = 0; kt < NT; kt++) {
        __syncthreads();   // all warps done with the stage we're about to overwrite
        if (kt + 2 < NT) {
            int st = (kt + 2) % NSTAGE;
            gemm_issue(smbase + st * STG_WORDS * 4,
                       smbase + (st * STG_WORDS + 32 * GP) * 4,
                       At, Bt, ldA, ldB, kt + 2, bm, bn, tid);
        }
        CP_COMMIT();       // always commit (empty ok) to keep group counting uniform
        CP_WAIT2();        // tile kt's group complete (<=2 newer groups pending)
        __syncthreads();

        const unsigned* As = sm + (kt % NSTAGE) * STG_WORDS;
        const unsigned* Bs = As + 32 * GP;

        #pragma unroll
        for (int ks = 0; ks < 32; ks += 8) {
            unsigned a[2][4];
            #pragma unroll
            for (int mt = 0; mt < 2; mt++) {
                int mrow = wm * 32 + mt * 16;
                a[mt][0] = As[(ks + tig    ) * GP + mrow + gid];
                a[mt][1] = As[(ks + tig    ) * GP + mrow + gid + 8];
                a[mt][2] = As[(ks + tig + 4) * GP + mrow + gid];
                a[mt][3] = As[(ks + tig + 4) * GP + mrow + gid + 8];
            }
            unsigned b[8][2];
            #pragma unroll
            for (int nt = 0; nt < 8; nt++) {
                int ncol = wn * 64 + nt * 8;
                b[nt][0] = Bs[(ks + tig    ) * GP + ncol + gid];
                b[nt][1] = Bs[(ks + tig + 4) * GP + ncol + gid];
            }
            #pragma unroll
            for (int mt = 0; mt < 2; mt++)
                #pragma unroll
                for (int nt = 0; nt < 8; nt++)
                    mma_tf32(acc[mt][nt],
                             a[mt][0], a[mt][1], a[mt][2], a[mt][3],
                             b[nt][0], b[nt][1]);
        }
    }

    // ---- epilogue: pick destination ----
    float* C;
    int ldc, cb;
    if (QKV) {
        if (bn < NQ)            { C = C0; ldc = NQ;  cb = bn; }
        else if (bn < NQ + NKV) { C = C1; ldc = NKV; cb = bn - NQ; }
        else                    { C = C2; ldc = NKV; cb = bn - NQ - NKV; }
    } else {
        C = C0; ldc = ldc_plain; cb = bn;
    }

    #pragma unroll
    for (int mt = 0; mt < 2; mt++) {
        #pragma unroll
        for (int nt = 0; nt < 8; nt++) {
            int r0 = bm + wm * 32 + mt * 16 + gid;
            int c0 = cb + wn * 64 + nt * 8 + tig * 2;
            *(float2*)&C[(size_t)r0       * ldc + c0] = make_float2(acc[mt][nt][0], acc[mt][nt][1]);
            *(float2*)&C[(size_t)(r0 + 8) * ldc + c0] = make_float2(acc[mt][nt][2], acc[mt][nt][3]);
        }
    }
}

// ---------------- fused flash attention (tf32 mma, online softmax) ----------------
#define QS_PAD 132
#define KS_PAD 132
#define VS_PAD 136
#define SM_QS  0
#define SM_KS  (128 * QS_PAD)
#define SM_VS  (SM_KS + 64 * KS_PAD)
#define SM_TOT ((SM_VS + 64 * VS_PAD) * 4)   // bytes = 136192

__global__ __launch_bounds__(256, 1)
void flash_kernel(const float* __restrict__ q,
                  const float* __restrict__ k,
                  const float* __restrict__ v,
                  float* __restrict__ y)
{
    extern __shared__ unsigned smf[];
    unsigned* Qs = smf + SM_QS;
    unsigned* Ks = smf + SM_KS;
    unsigned* Vs = smf + SM_VS;

    const int head = blockIdx.x;
    const int kh   = head / GRP;
    const int bq   = (gridDim.y - 1) - blockIdx.y;   // heavy blocks first

    const int tid  = threadIdx.x;
    const int lane = tid & 31;
    const int wid  = tid >> 5;
    const int gid  = lane >> 2;
    const int tig  = lane & 3;

    #pragma unroll
    for (int i = 0; i < 16; i++) {
        int f   = tid + i * 256;
        int row = f >> 5;
        int c4  = f & 31;
        float4 t = *(const float4*)&q[(size_t)(bq * 128 + row) * NQ + head * HD + c4 * 4];
        *(uint4*)&Qs[row * QS_PAD + c4 * 4] =
            make_uint4(f2tf32(t.x), f2tf32(t.y), f2tf32(t.z), f2tf32(t.w));
    }

    float Oa[16][4];
    #pragma unroll
    for (int nt = 0; nt < 16; nt++)
        #pragma unroll
        for (int r = 0; r < 4; r++)
            Oa[nt][r] = 0.0f;
    float mrow0 = -1e30f, mrow1 = -1e30f;
    float lrow0 = 0.0f,   lrow1 = 0.0f;

    const int i0 = bq * 128 + wid * 16 + gid;
    const int nkb = 2 * (bq + 1);

    for (int kb = 0; kb < nkb; kb++) {
        const int k0 = kb * 64;

        __syncthreads();
        #pragma unroll
        for (int i = 0; i < 8; i++) {
            int f   = tid + i * 256;
            int key = f >> 5;
            int c4  = f & 31;
            size_t goff = (size_t)(k0 + key) * NKV + kh * HD + c4 * 4;
            float4 tk = *(const float4*)&k[goff];
            *(uint4*)&Ks[key * KS_PAD + c4 * 4] =
                make_uint4(f2tf32(tk.x), f2tf32(tk.y), f2tf32(tk.z), f2tf32(tk.w));
            float4 tv = *(const float4*)&v[goff];
            *(uint4*)&Vs[key * VS_PAD + c4 * 4] =
                make_uint4(f2tf32(tv.x), f2tf32(tv.y), f2tf32(tv.z), f2tf32(tv.w));
        }
        __syncthreads();

        float s[8][4];
        #pragma unroll
        for (int nt = 0; nt < 8; nt++)
            #pragma unroll
            for (int r = 0; r < 4; r++)
                s[nt][r] = 0.0f;

        #pragma unroll
        for (int ks = 0; ks < 128; ks += 8) {
            unsigned a0 = Qs[(wid * 16 + gid    ) * QS_PAD + ks + tig];
            unsigned a1 = Qs[(wid * 16 + gid + 8) * QS_PAD + ks + tig];
            unsigned a2 = Qs[(wid * 16 + gid    ) * QS_PAD + ks + tig + 4];
            unsigned a3 = Qs[(wid * 16 + gid + 8) * QS_PAD + ks + tig + 4];
            #pragma unroll
            for (int nt = 0; nt < 8; nt++) {
                unsigned b0 = Ks[(nt * 8 + gid) * KS_PAD + ks + tig];
                unsigned b1 = Ks[(nt * 8 + gid) * KS_PAD + ks + tig + 4];
                mma_tf32(s[nt], a0, a1, a2, a3, b0, b1);
            }
        }

        const bool diag = (k0 + 64 > bq * 128);
        #pragma unroll
        for (int nt = 0; nt < 8; nt++) {
            int j = k0 + nt * 8 + tig * 2;
            #pragma unroll
            for (int r = 0; r < 4; r++) {
                int jj = j + (r & 1);
                int ii = i0 + ((r >> 1) << 3);
                float val = s[nt][r] * SCALEV;
                if (diag && jj > ii) val = -1e30f;
                s[nt][r] = val;
            }
        }

        float mx0 = -1e30f, mx1 = -1e30f;
        #pragma unroll
        for (int nt = 0; nt < 8; nt++) {
            mx0 = fmaxf(mx0, fmaxf(s[nt][0], s[nt][1]));
            mx1 = fmaxf(mx1, fmaxf(s[nt][2], s[nt][3]));
        }
        mx0 = fmaxf(mx0, __shfl_xor_sync(0xffffffffu, mx0, 1));
        mx0 = fmaxf(mx0, __shfl_xor_sync(0xffffffffu, mx0, 2));
        mx1 = fmaxf(mx1, __shfl_xor_sync(0xffffffffu, mx1, 1));
        mx1 = fmaxf(mx1, __shfl_xor_sync(0xffffffffu, mx1, 2));

        float mnew0 = fmaxf(mrow0, mx0);
        float mnew1 = fmaxf(mrow1, mx1);
        float corr0 = __expf(mrow0 - mnew0);
        float corr1 = __expf(mrow1 - mnew1);
        mrow0 = mnew0; mrow1 = mnew1;

        float sum0 = 0.0f, sum1 = 0.0f;
        #pragma unroll
        for (int nt = 0; nt < 8; nt++) {
            s[nt][0] = __expf(s[nt][0] - mnew0);
            s[nt][1] = __expf(s[nt][1] - mnew0);
            s[nt][2] = __expf(s[nt][2] - mnew1);
            s[nt][3] = __expf(s[nt][3] - mnew1);
            sum0 += s[nt][0] + s[nt][1];
            sum1 += s[nt][2] + s[nt][3];
        }
        sum0 += __shfl_xor_sync(0xffffffffu, sum0, 1);
        sum0 += __shfl_xor_sync(0xffffffffu, sum0, 2);
        sum1 += __shfl_xor_sync(0xffffffffu, sum1, 1);
        sum1 += __shfl_xor_sync(0xffffffffu, sum1, 2);
        lrow0 = lrow0 * corr0 + sum0;
        lrow1 = lrow1 * corr1 + sum1;

        #pragma unroll
        for (int nt = 0; nt < 16; nt++) {
            Oa[nt][0] *= corr0;  Oa[nt][1] *= corr0;
            Oa[nt][2] *= corr1;  Oa[nt][3] *= corr1;
        }

        const int srcA = (lane & ~3) | (tig >> 1);
        const int srcB = srcA + 2;
        const bool odd = (tig & 1);
        #pragma unroll
        for (int ks8 = 0; ks8 < 8; ks8++) {
            unsigned p0 = f2tf32(s[ks8][0]);
            unsigned p1 = f2tf32(s[ks8][1]);
            unsigned p2 = f2tf32(s[ks8][2]);
            unsigned p3 = f2tf32(s[ks8][3]);
            unsigned x0 = __shfl_sync(0xffffffffu, p0, srcA);
            unsigned x1 = __shfl_sync(0xffffffffu, p1, srcA);
            unsigned x2 = __shfl_sync(0xffffffffu, p2, srcA);
            unsigned x3 = __shfl_sync(0xffffffffu, p3, srcA);
            unsigned y0 = __shfl_sync(0xffffffffu, p0, srcB);
            unsigned y1 = __shfl_sync(0xffffffffu, p1, srcB);
            unsigned y2 = __shfl_sync(0xffffffffu, p2, srcB);
            unsigned y3 = __shfl_sync(0xffffffffu, p3, srcB);
            unsigned a0 = odd ? x1 : x0;
            unsigned a1 = odd ? x3 : x2;
            unsigned a2 = odd ? y1 : y0;
            unsigned a3 = odd ? y3 : y2;
            #pragma unroll
            for (int nt = 0; nt < 16; nt++) {
                unsigned b0 = Vs[(ks8 * 8 + tig    ) * VS_PAD + nt * 8 + gid];
                unsigned b1 = Vs[(ks8 * 8 + tig + 4) * VS_PAD + nt * 8 + gid];
                mma_tf32(Oa[nt], a0, a1, a2, a3, b0, b1);
            }
        }
    }

    float inv0 = 1.0f / lrow0;
    float inv1 = 1.0f / lrow1;
    #pragma unroll
    for (int nt = 0; nt < 16; nt++) {
        int c0 = head * HD + nt * 8 + tig * 2;
        *(float2*)&y[(size_t)i0       * NQ + c0] = make_float2(Oa[nt][0] * inv0, Oa[nt][1] * inv0);
        *(float2*)&y[(size_t)(i0 + 8) * NQ + c0] = make_float2(Oa[nt][2] * inv1, Oa[nt][3] * inv1);
    }
}

// ---------------- RMSNorm + RoPE: one warp per (s, h) row ----------------
__global__ __launch_bounds__(128)
void norm_rope_kernel(float* __restrict__ x,
                      const float* __restrict__ w,
                      const float* __restrict__ pcos,
                      const float* __restrict__ psin,
                      int nh)
{
    const int idx  = blockIdx.x * 4 + (threadIdx.x >> 5);
    const int lane = threadIdx.x & 31;
    const int s    = idx / nh;

    float* row = x + (size_t)idx * HD;
    float4 val = *(float4*)&row[lane * 4];

    float ssq = val.x * val.x + val.y * val.y + val.z * val.z + val.w * val.w;
    #pragma unroll
    for (int off = 16; off > 0; off >>= 1)
        ssq += __shfl_xor_sync(0xffffffffu, ssq, off);

    float r = rsqrtf(ssq * (1.0f / HD) + EPSV);
    float4 wv = *(const float4*)&w[lane * 4];
    float4 xn = make_float4(val.x * r * wv.x, val.y * r * wv.y,
                            val.z * r * wv.z, val.w * r * wv.w);

    float px = __shfl_xor_sync(0xffffffffu, xn.x, 16);
    float py = __shfl_xor_sync(0xffffffffu, xn.y, 16);
    float pz = __shfl_xor_sync(0xffffffffu, xn.z, 16);
    float pw = __shfl_xor_sync(0xffffffffu, xn.w, 16);

    const int cidx = (lane & 15) * 4;
    float4 cv = *(const float4*)&pcos[s * 64 + cidx];
    float4 sv = *(const float4*)&psin[s * 64 + cidx];

    float4 o;
    if (lane < 16) {
        o = make_float4(xn.x * cv.x - px * sv.x, xn.y * cv.y - py * sv.y,
                        xn.z * cv.z - pz * sv.z, xn.w * cv.w - pw * sv.w);
    } else {
        o = make_float4(px * sv.x + xn.x * cv.x, py * sv.y + xn.y * cv.y,
                        pz * sv.z + xn.z * cv.z, pw * sv.w + xn.w * cv.w);
    }
    *(float4*)&row[lane * 4] = o;
}

// ---------------- k_new / v_new tail copy ----------------
__global__ void tail_copy_kernel(const float* __restrict__ k,
                                 const float* __restrict__ v,
                                 float* __restrict__ out)
{
    int t = blockIdx.x * blockDim.x + threadIdx.x;
    const size_t base = (size_t)Sq * HIDN;
    if (t < NKV)
        out[base + t] = k[(size_t)(Sq - 1) * NKV + t];
    else
        out[base + t] = v[(size_t)(Sq - 1) * NKV + (t - NKV)];
}

// ---------------- launcher ----------------
extern "C" void kernel_launch(void* const* d_in, const int* in_sizes, int n_in,
                              void* d_out, int out_size)
{
    const float* hs   = (const float*)d_in[0];
    const float* pcos = (const float*)d_in[1];
    const float* psin = (const float*)d_in[2];
    // d_in[3] = atten_mask (causal, reproduced arithmetically)
    const float* Wq   = (const float*)d_in[4];
    const float* Wk   = (const float*)d_in[5];
    const float* Wv   = (const float*)d_in[6];
    const float* Wo   = (const float*)d_in[7];
    const float* qw   = (const float*)d_in[8];
    const float* kw   = (const float*)d_in[9];
    float* out = (float*)d_out;

    float *q, *k, *v, *y;
    unsigned *hsT, *wqkvT, *woT, *yT;
    cudaGetSymbolAddress((void**)&q,     g_q);
    cudaGetSymbolAddress((void**)&k,     g_k);
    cudaGetSymbolAddress((void**)&v,     g_v);
    cudaGetSymbolAddress((void**)&y,     g_y);
    cudaGetSymbolAddress((void**)&hsT,   g_hsT);
    cudaGetSymbolAddress((void**)&wqkvT, g_wqkvT);
    cudaGetSymbolAddress((void**)&woT,   g_woT);
    cudaGetSymbolAddress((void**)&yT,    g_yT);

    cudaFuncSetAttribute(mma_gemm<true>,
                         cudaFuncAttributeMaxDynamicSharedMemorySize, GEMM_SMEM);
    cudaFuncSetAttribute(mma_gemm<false>,
                         cudaFuncAttributeMaxDynamicSharedMemorySize, GEMM_SMEM);
    cudaFuncSetAttribute(flash_kernel,
                         cudaFuncAttributeMaxDynamicSharedMemorySize, SM_TOT);

    // ---- transposes + tf32 convert ----
    transpose_tf32_kernel<<<dim3(64, 64), 256>>>(hs, hsT,   HIDN, Sq,   0);      // hs[m][k] -> hsT[k][m]
    transpose_tf32_kernel<<<dim3(64, 64), 256>>>(Wq, wqkvT, HIDN, NQKV, 0);      // Wq[n][k] -> [k][n]
    transpose_tf32_kernel<<<dim3(64, 32), 256>>>(Wk, wqkvT, HIDN, NQKV, NQ);
    transpose_tf32_kernel<<<dim3(64, 32), 256>>>(Wv, wqkvT, HIDN, NQKV, NQ + NKV);
    transpose_tf32_kernel<<<dim3(64, 64), 256>>>(Wo, woT,   NQ,   HIDN, 0);

    // ---- fused QKV projection ----
    mma_gemm<true><<<dim3(NQKV / 128, Sq / 128), 256, GEMM_SMEM>>>(
        hsT, wqkvT, q, k, v, Sq, NQKV, HIDN, 0);

    // ---- RMSNorm + RoPE ----
    norm_rope_kernel<<<Sq * NH  / 4, 128>>>(q, qw, pcos, psin, NH);
    norm_rope_kernel<<<Sq * NKH / 4, 128>>>(k, kw, pcos, psin, NKH);

    // ---- fused attention ----
    flash_kernel<<<dim3(NH, Sq / 128), 256, SM_TOT>>>(q, k, v, y);

    // ---- y -> yT, then output projection ----
    transpose_tf32_kernel<<<dim3(64, 64), 256>>>(y, yT, NQ, Sq, 0);
    mma_gemm<false><<<dim3(HIDN / 128, Sq / 128), 256, GEMM_SMEM>>>(
        yT, woT, out, nullptr, nullptr, Sq, HIDN, NQ, HIDN);

    // ---- k_new / v_new ----
    tail_copy_kernel<<<8, 256>>>(k, v, out);
}

// round 9
// speedup vs baseline: 1.9099x; 1.0352x over previous
#include <cuda_runtime.h>
#include <cuda_bf16.h>
#include <math.h>

// Problem constants
#define Sq    2048
#define HIDN  2048
#define NH    16
#define NKH   8
#define HD    128
#define GRP   2          // NH / NKH
#define EPSV  1e-6f
#define SCALEV 0.08838834764831845f   // 128^-0.5

#define NQ (NH * HD)     // 2048
#define NKV (NKH * HD)   // 1024
#define NQKV (NQ + 2 * NKV)  // 4096

// ---------------- static device scratch (allocation-free rule) ----------------
__device__ float g_q[Sq * NQ];
__device__ float g_k[Sq * NKV];
__device__ float g_v[Sq * NKV];
__device__ float g_y[Sq * NQ];
__device__ unsigned g_hsT[HIDN * Sq];        // tf32, [k][m]
__device__ unsigned g_wqkvT[HIDN * NQKV];    // tf32, [k][n]  (Wq|Wk|Wv)
__device__ unsigned g_woT[NQ * HIDN];        // tf32, [k][n]
__device__ unsigned g_yT[NQ * Sq];           // tf32, [k][m]
__device__ unsigned g_q32[Sq * NQ];          // tf32 post norm+rope
__device__ unsigned g_k32[Sq * NKV];         // tf32 post norm+rope
__device__ unsigned g_v32[Sq * NKV];         // tf32 raw v

// ---------------- tf32 helpers ----------------
__device__ __forceinline__ unsigned f2tf32(float f) {
    unsigned u;
    asm("cvt.rna.tf32.f32 %0, %1;" : "=r"(u) : "f"(f));
    return u;
}

__device__ __forceinline__ void mma_tf32(float c[4],
                                         unsigned a0, unsigned a1, unsigned a2, unsigned a3,
                                         unsigned b0, unsigned b1)
{
    asm volatile(
        "mma.sync.aligned.m16n8k8.row.col.f32.tf32.tf32.f32 "
        "{%0,%1,%2,%3}, {%4,%5,%6,%7}, {%8,%9}, {%0,%1,%2,%3};"
        : "+f"(c[0]), "+f"(c[1]), "+f"(c[2]), "+f"(c[3])
        : "r"(a0), "r"(a1), "r"(a2), "r"(a3), "r"(b0), "r"(b1));
}

__device__ __forceinline__ void cpa16(unsigned dst, const unsigned* src) {
    asm volatile("cp.async.cg.shared.global [%0], [%1], 16;\n" :: "r"(dst), "l"(src));
}
#define CP_COMMIT() asm volatile("cp.async.commit_group;\n")
#define CP_WAIT2()  asm volatile("cp.async.wait_group 2;\n")
#define CP_WAIT1()  asm volatile("cp.async.wait_group 1;\n")

// ---------------- transpose + tf32 convert ----------------
__global__ __launch_bounds__(256)
void transpose_tf32_kernel(const float* __restrict__ in, unsigned* __restrict__ out,
                           int ldin, int ldout, int coloff)
{
    __shared__ float t[32][33];
    const int c0 = blockIdx.x * 32;
    const int r0 = blockIdx.y * 32;
    const int tx = threadIdx.x & 31;
    const int ty = threadIdx.x >> 5;   // 0..7

    #pragma unroll
    for (int i = 0; i < 32; i += 8)
        t[ty + i][tx] = in[(size_t)(r0 + ty + i) * ldin + c0 + tx];
    __syncthreads();
    #pragma unroll
    for (int i = 0; i < 32; i += 8)
        out[(size_t)(c0 + ty + i) * ldout + coloff + r0 + tx] = f2tf32(t[tx][ty + i]);
}

// ---------------- cp.async 3-stage pipelined tf32 GEMM ----------------
#define GP 136
#define STG_WORDS (2 * 32 * GP)
#define NSTAGE 3
#define GEMM_SMEM (NSTAGE * STG_WORDS * 4)   // 104448 bytes

__device__ __forceinline__ void gemm_issue(unsigned smA, unsigned smB,
                                           const unsigned* At, const unsigned* Bt,
                                           int ldA, int ldB, int kt,
                                           int bm, int bn, int tid)
{
    #pragma unroll
    for (int i = 0; i < 4; i++) {
        int e  = tid + i * 256;
        int kk = e >> 5;
        int mc = e & 31;
        cpa16(smA + (unsigned)(kk * GP + mc * 4) * 4,
              At + (size_t)(kt * 32 + kk) * ldA + bm + mc * 4);
        cpa16(smB + (unsigned)(kk * GP + mc * 4) * 4,
              Bt + (size_t)(kt * 32 + kk) * ldB + bn + mc * 4);
    }
}

template <bool QKV>
__global__ __launch_bounds__(256, 2)
void mma_gemm(const unsigned* __restrict__ At, const unsigned* __restrict__ Bt,
              float* __restrict__ C0, float* __restrict__ C1, float* __restrict__ C2,
              unsigned* __restrict__ Ct,   // tf32 mirror for v region (QKV only)
              int ldA, int ldB, int K, int ldc_plain)
{
    extern __shared__ unsigned sm[];
    const unsigned smbase = (unsigned)__cvta_generic_to_shared(sm);

    const int bm = blockIdx.y * 128;
    const int bn = blockIdx.x * 128;

    const int tid  = threadIdx.x;
    const int lane = tid & 31;
    const int wid  = tid >> 5;
    const int wm   = wid & 3;
    const int wn   = wid >> 2;
    const int gid  = lane >> 2;
    const int tig  = lane & 3;

    float acc[2][8][4];
    #pragma unroll
    for (int mt = 0; mt < 2; mt++)
        #pragma unroll
        for (int nt = 0; nt < 8; nt++)
            #pragma unroll
            for (int r = 0; r < 4; r++)
                acc[mt][nt][r] = 0.0f;

    const int NT = K / 32;

    gemm_issue(smbase, smbase + 32 * GP * 4, At, Bt, ldA, ldB, 0, bm, bn, tid);
    CP_COMMIT();
    gemm_issue(smbase + STG_WORDS * 4, smbase + (STG_WORDS + 32 * GP) * 4,
               At, Bt, ldA, ldB, 1, bm, bn, tid);
    CP_COMMIT();

    for (int kt = 0; kt < NT; kt++) {
        __syncthreads();
        if (kt + 2 < NT) {
            int st = (kt + 2) % NSTAGE;
            gemm_issue(smbase + st * STG_WORDS * 4,
                       smbase + (st * STG_WORDS + 32 * GP) * 4,
                       At, Bt, ldA, ldB, kt + 2, bm, bn, tid);
        }
        CP_COMMIT();
        CP_WAIT2();
        __syncthreads();

        const unsigned* As = sm + (kt % NSTAGE) * STG_WORDS;
        const unsigned* Bs = As + 32 * GP;

        #pragma unroll
        for (int ks = 0; ks < 32; ks += 8) {
            unsigned a[2][4];
            #pragma unroll
            for (int mt = 0; mt < 2; mt++) {
                int mrow = wm * 32 + mt * 16;
                a[mt][0] = As[(ks + tig    ) * GP + mrow + gid];
                a[mt][1] = As[(ks + tig    ) * GP + mrow + gid + 8];
                a[mt][2] = As[(ks + tig + 4) * GP + mrow + gid];
                a[mt][3] = As[(ks + tig + 4) * GP + mrow + gid + 8];
            }
            unsigned b[8][2];
            #pragma unroll
            for (int nt = 0; nt < 8; nt++) {
                int ncol = wn * 64 + nt * 8;
                b[nt][0] = Bs[(ks + tig    ) * GP + ncol + gid];
                b[nt][1] = Bs[(ks + tig + 4) * GP + ncol + gid];
            }
            #pragma unroll
            for (int mt = 0; mt < 2; mt++)
                #pragma unroll
                for (int nt = 0; nt < 8; nt++)
                    mma_tf32(acc[mt][nt],
                             a[mt][0], a[mt][1], a[mt][2], a[mt][3],
                             b[nt][0], b[nt][1]);
        }
    }

    // ---- epilogue ----
    float* C;
    int ldc, cb;
    bool isv = false;
    if (QKV) {
        if (bn < NQ)            { C = C0; ldc = NQ;  cb = bn; }
        else if (bn < NQ + NKV) { C = C1; ldc = NKV; cb = bn - NQ; }
        else                    { C = C2; ldc = NKV; cb = bn - NQ - NKV; isv = true; }
    } else {
        C = C0; ldc = ldc_plain; cb = bn;
    }

    #pragma unroll
    for (int mt = 0; mt < 2; mt++) {
        #pragma unroll
        for (int nt = 0; nt < 8; nt++) {
            int r0 = bm + wm * 32 + mt * 16 + gid;
            int c0 = cb + wn * 64 + nt * 8 + tig * 2;
            *(float2*)&C[(size_t)r0       * ldc + c0] = make_float2(acc[mt][nt][0], acc[mt][nt][1]);
            *(float2*)&C[(size_t)(r0 + 8) * ldc + c0] = make_float2(acc[mt][nt][2], acc[mt][nt][3]);
            if (QKV && isv) {
                *(uint2*)&Ct[(size_t)r0       * ldc + c0] =
                    make_uint2(f2tf32(acc[mt][nt][0]), f2tf32(acc[mt][nt][1]));
                *(uint2*)&Ct[(size_t)(r0 + 8) * ldc + c0] =
                    make_uint2(f2tf32(acc[mt][nt][2]), f2tf32(acc[mt][nt][3]));
            }
        }
    }
}

// ---------------- fused flash attention (cp.async double-buffered K/V) ----------------
#define QS_PAD 132
#define KS_PAD 132
#define VS_PAD 136
#define FKV_WORDS (64 * KS_PAD + 64 * VS_PAD)          // one K+V stage = 17152
#define SMF_Q 0
#define SMF_KV(st) (128 * QS_PAD + (st) * FKV_WORDS)   // K first, then V
#define SM_TOT ((128 * QS_PAD + 2 * FKV_WORDS) * 4)    // 204800 bytes

__device__ __forceinline__ void flash_issue_kv(unsigned smK, unsigned smV,
                                               const unsigned* k32, const unsigned* v32,
                                               int k0, int kh, int tid)
{
    #pragma unroll
    for (int i = 0; i < 8; i++) {
        int f   = tid + i * 256;
        int key = f >> 5;
        int c4  = f & 31;
        size_t goff = (size_t)(k0 + key) * NKV + kh * HD + c4 * 4;
        cpa16(smK + (unsigned)(key * KS_PAD + c4 * 4) * 4, k32 + goff);
        cpa16(smV + (unsigned)(key * VS_PAD + c4 * 4) * 4, v32 + goff);
    }
}

__global__ __launch_bounds__(256, 1)
void flash_kernel(const unsigned* __restrict__ q32,
                  const unsigned* __restrict__ k32,
                  const unsigned* __restrict__ v32,
                  float* __restrict__ y)
{
    extern __shared__ unsigned smf[];
    const unsigned smfb = (unsigned)__cvta_generic_to_shared(smf);
    unsigned* Qs = smf + SMF_Q;

    const int head = blockIdx.x;
    const int kh   = head / GRP;
    const int bq   = (gridDim.y - 1) - blockIdx.y;   // heavy blocks first

    const int tid  = threadIdx.x;
    const int lane = tid & 31;
    const int wid  = tid >> 5;
    const int gid  = lane >> 2;
    const int tig  = lane & 3;

    // ---- group 0: Q tile (128 rows x 32 float4 = 4096 transfers -> 16 iters) + KV tile 0 ----
    #pragma unroll
    for (int i = 0; i < 16; i++) {
        int f   = tid + i * 256;
        int row = f >> 5;          // 0..127
        int c4  = f & 31;
        cpa16(smfb + (unsigned)(row * QS_PAD + c4 * 4) * 4,
              q32 + (size_t)(bq * 128 + row) * NQ + head * HD + c4 * 4);
    }
    flash_issue_kv(smfb + SMF_KV(0) * 4, smfb + (SMF_KV(0) + 64 * KS_PAD) * 4,
                   k32, v32, 0, kh, tid);
    CP_COMMIT();

    float Oa[16][4];
    #pragma unroll
    for (int nt = 0; nt < 16; nt++)
        #pragma unroll
        for (int r = 0; r < 4; r++)
            Oa[nt][r] = 0.0f;
    float mrow0 = -1e30f, mrow1 = -1e30f;
    float lrow0 = 0.0f,   lrow1 = 0.0f;

    const int i0 = bq * 128 + wid * 16 + gid;
    const int nkb = 2 * (bq + 1);

    for (int kb = 0; kb < nkb; kb++) {
        const int k0 = kb * 64;

        // ---- prefetch next KV tile ----
        if (kb + 1 < nkb) {
            int st = (kb + 1) & 1;
            flash_issue_kv(smfb + SMF_KV(st) * 4,
                           smfb + (SMF_KV(st) + 64 * KS_PAD) * 4,
                           k32, v32, k0 + 64, kh, tid);
        }
        CP_COMMIT();
        CP_WAIT1();          // tile kb (and Q) complete
        __syncthreads();

        const unsigned* Ks = smf + SMF_KV(kb & 1);
        const unsigned* Vs = Ks + 64 * KS_PAD;

        // ---- S = Q @ K^T ----
        float s[8][4];
        #pragma unroll
        for (int nt = 0; nt < 8; nt++)
            #pragma unroll
            for (int r = 0; r < 4; r++)
                s[nt][r] = 0.0f;

        #pragma unroll
        for (int ks = 0; ks < 128; ks += 8) {
            unsigned a0 = Qs[(wid * 16 + gid    ) * QS_PAD + ks + tig];
            unsigned a1 = Qs[(wid * 16 + gid + 8) * QS_PAD + ks + tig];
            unsigned a2 = Qs[(wid * 16 + gid    ) * QS_PAD + ks + tig + 4];
            unsigned a3 = Qs[(wid * 16 + gid + 8) * QS_PAD + ks + tig + 4];
            #pragma unroll
            for (int nt = 0; nt < 8; nt++) {
                unsigned b0 = Ks[(nt * 8 + gid) * KS_PAD + ks + tig];
                unsigned b1 = Ks[(nt * 8 + gid) * KS_PAD + ks + tig + 4];
                mma_tf32(s[nt], a0, a1, a2, a3, b0, b1);
            }
        }

        // ---- scale + causal mask ----
        const bool diag = (k0 + 64 > bq * 128);
        #pragma unroll
        for (int nt = 0; nt < 8; nt++) {
            int j = k0 + nt * 8 + tig * 2;
            #pragma unroll
            for (int r = 0; r < 4; r++) {
                int jj = j + (r & 1);
                int ii = i0 + ((r >> 1) << 3);
                float val = s[nt][r] * SCALEV;
                if (diag && jj > ii) val = -1e30f;
                s[nt][r] = val;
            }
        }

        // ---- online softmax ----
        float mx0 = -1e30f, mx1 = -1e30f;
        #pragma unroll
        for (int nt = 0; nt < 8; nt++) {
            mx0 = fmaxf(mx0, fmaxf(s[nt][0], s[nt][1]));
            mx1 = fmaxf(mx1, fmaxf(s[nt][2], s[nt][3]));
        }
        mx0 = fmaxf(mx0, __shfl_xor_sync(0xffffffffu, mx0, 1));
        mx0 = fmaxf(mx0, __shfl_xor_sync(0xffffffffu, mx0, 2));
        mx1 = fmaxf(mx1, __shfl_xor_sync(0xffffffffu, mx1, 1));
        mx1 = fmaxf(mx1, __shfl_xor_sync(0xffffffffu, mx1, 2));

        float mnew0 = fmaxf(mrow0, mx0);
        float mnew1 = fmaxf(mrow1, mx1);
        float corr0 = __expf(mrow0 - mnew0);
        float corr1 = __expf(mrow1 - mnew1);
        mrow0 = mnew0; mrow1 = mnew1;

        float sum0 = 0.0f, sum1 = 0.0f;
        #pragma unroll
        for (int nt = 0; nt < 8; nt++) {
            s[nt][0] = __expf(s[nt][0] - mnew0);
            s[nt][1] = __expf(s[nt][1] - mnew0);
            s[nt][2] = __expf(s[nt][2] - mnew1);
            s[nt][3] = __expf(s[nt][3] - mnew1);
            sum0 += s[nt][0] + s[nt][1];
            sum1 += s[nt][2] + s[nt][3];
        }
        sum0 += __shfl_xor_sync(0xffffffffu, sum0, 1);
        sum0 += __shfl_xor_sync(0xffffffffu, sum0, 2);
        sum1 += __shfl_xor_sync(0xffffffffu, sum1, 1);
        sum1 += __shfl_xor_sync(0xffffffffu, sum1, 2);
        lrow0 = lrow0 * corr0 + sum0;
        lrow1 = lrow1 * corr1 + sum1;

        #pragma unroll
        for (int nt = 0; nt < 16; nt++) {
            Oa[nt][0] *= corr0;  Oa[nt][1] *= corr0;
            Oa[nt][2] *= corr1;  Oa[nt][3] *= corr1;
        }

        // ---- O += P @ V ----
        const int srcA = (lane & ~3) | (tig >> 1);
        const int srcB = srcA + 2;
        const bool odd = (tig & 1);
        #pragma unroll
        for (int ks8 = 0; ks8 < 8; ks8++) {
            unsigned p0 = f2tf32(s[ks8][0]);
            unsigned p1 = f2tf32(s[ks8][1]);
            unsigned p2 = f2tf32(s[ks8][2]);
            unsigned p3 = f2tf32(s[ks8][3]);
            unsigned x0 = __shfl_sync(0xffffffffu, p0, srcA);
            unsigned x1 = __shfl_sync(0xffffffffu, p1, srcA);
            unsigned x2 = __shfl_sync(0xffffffffu, p2, srcA);
            unsigned x3 = __shfl_sync(0xffffffffu, p3, srcA);
            unsigned y0 = __shfl_sync(0xffffffffu, p0, srcB);
            unsigned y1 = __shfl_sync(0xffffffffu, p1, srcB);
            unsigned y2 = __shfl_sync(0xffffffffu, p2, srcB);
            unsigned y3 = __shfl_sync(0xffffffffu, p3, srcB);
            unsigned a0 = odd ? x1 : x0;
            unsigned a1 = odd ? x3 : x2;
            unsigned a2 = odd ? y1 : y0;
            unsigned a3 = odd ? y3 : y2;
            #pragma unroll
            for (int nt = 0; nt < 16; nt++) {
                unsigned b0 = Vs[(ks8 * 8 + tig    ) * VS_PAD + nt * 8 + gid];
                unsigned b1 = Vs[(ks8 * 8 + tig + 4) * VS_PAD + nt * 8 + gid];
                mma_tf32(Oa[nt], a0, a1, a2, a3, b0, b1);
            }
        }
        __syncthreads();   // all warps done with stage (kb&1) before it is re-issued
    }

    float inv0 = 1.0f / lrow0;
    float inv1 = 1.0f / lrow1;
    #pragma unroll
    for (int nt = 0; nt < 16; nt++) {
        int c0 = head * HD + nt * 8 + tig * 2;
        *(float2*)&y[(size_t)i0       * NQ + c0] = make_float2(Oa[nt][0] * inv0, Oa[nt][1] * inv0);
        *(float2*)&y[(size_t)(i0 + 8) * NQ + c0] = make_float2(Oa[nt][2] * inv1, Oa[nt][3] * inv1);
    }
}

// ---------------- RMSNorm + RoPE -> tf32 (optionally keep fp32 in place) ----------------
template <bool KEEP_F32>
__global__ __launch_bounds__(128)
void norm_rope_kernel(float* __restrict__ x, unsigned* __restrict__ xt,
                      const float* __restrict__ w,
                      const float* __restrict__ pcos,
                      const float* __restrict__ psin,
                      int nh)
{
    const int idx  = blockIdx.x * 4 + (threadIdx.x >> 5);
    const int lane = threadIdx.x & 31;
    const int s    = idx / nh;

    float* row = x + (size_t)idx * HD;
    float4 val = *(float4*)&row[lane * 4];

    float ssq = val.x * val.x + val.y * val.y + val.z * val.z + val.w * val.w;
    #pragma unroll
    for (int off = 16; off > 0; off >>= 1)
        ssq += __shfl_xor_sync(0xffffffffu, ssq, off);

    float r = rsqrtf(ssq * (1.0f / HD) + EPSV);
    float4 wv = *(const float4*)&w[lane * 4];
    float4 xn = make_float4(val.x * r * wv.x, val.y * r * wv.y,
                            val.z * r * wv.z, val.w * r * wv.w);

    float px = __shfl_xor_sync(0xffffffffu, xn.x, 16);
    float py = __shfl_xor_sync(0xffffffffu, xn.y, 16);
    float pz = __shfl_xor_sync(0xffffffffu, xn.z, 16);
    float pw = __shfl_xor_sync(0xffffffffu, xn.w, 16);

    const int cidx = (lane & 15) * 4;
    float4 cv = *(const float4*)&pcos[s * 64 + cidx];
    float4 sv = *(const float4*)&psin[s * 64 + cidx];

    float4 o;
    if (lane < 16) {
        o = make_float4(xn.x * cv.x - px * sv.x, xn.y * cv.y - py * sv.y,
                        xn.z * cv.z - pz * sv.z, xn.w * cv.w - pw * sv.w);
    } else {
        o = make_float4(px * sv.x + xn.x * cv.x, py * sv.y + xn.y * cv.y,
                        pz * sv.z + xn.z * cv.z, pw * sv.w + xn.w * cv.w);
    }
    if (KEEP_F32)
        *(float4*)&row[lane * 4] = o;
    *(uint4*)&xt[(size_t)idx * HD + lane * 4] =
        make_uint4(f2tf32(o.x), f2tf32(o.y), f2tf32(o.z), f2tf32(o.w));
}

// ---------------- k_new / v_new tail copy ----------------
__global__ void tail_copy_kernel(const float* __restrict__ k,
                                 const float* __restrict__ v,
                                 float* __restrict__ out)
{
    int t = blockIdx.x * blockDim.x + threadIdx.x;
    const size_t base = (size_t)Sq * HIDN;
    if (t < NKV)
        out[base + t] = k[(size_t)(Sq - 1) * NKV + t];
    else
        out[base + t] = v[(size_t)(Sq - 1) * NKV + (t - NKV)];
}

// ---------------- launcher ----------------
extern "C" void kernel_launch(void* const* d_in, const int* in_sizes, int n_in,
                              void* d_out, int out_size)
{
    const float* hs   = (const float*)d_in[0];
    const float* pcos = (const float*)d_in[1];
    const float* psin = (const float*)d_in[2];
    // d_in[3] = atten_mask (causal, reproduced arithmetically)
    const float* Wq   = (const float*)d_in[4];
    const float* Wk   = (const float*)d_in[5];
    const float* Wv   = (const float*)d_in[6];
    const float* Wo   = (const float*)d_in[7];
    const float* qw   = (const float*)d_in[8];
    const float* kw   = (const float*)d_in[9];
    float* out = (float*)d_out;

    float *q, *k, *v, *y;
    unsigned *hsT, *wqkvT, *woT, *yT, *q32, *k32, *v32;
    cudaGetSymbolAddress((void**)&q,     g_q);
    cudaGetSymbolAddress((void**)&k,     g_k);
    cudaGetSymbolAddress((void**)&v,     g_v);
    cudaGetSymbolAddress((void**)&y,     g_y);
    cudaGetSymbolAddress((void**)&hsT,   g_hsT);
    cudaGetSymbolAddress((void**)&wqkvT, g_wqkvT);
    cudaGetSymbolAddress((void**)&woT,   g_woT);
    cudaGetSymbolAddress((void**)&yT,    g_yT);
    cudaGetSymbolAddress((void**)&q32,   g_q32);
    cudaGetSymbolAddress((void**)&k32,   g_k32);
    cudaGetSymbolAddress((void**)&v32,   g_v32);

    cudaFuncSetAttribute(mma_gemm<true>,
                         cudaFuncAttributeMaxDynamicSharedMemorySize, GEMM_SMEM);
    cudaFuncSetAttribute(mma_gemm<false>,
                         cudaFuncAttributeMaxDynamicSharedMemorySize, GEMM_SMEM);
    cudaFuncSetAttribute(flash_kernel,
                         cudaFuncAttributeMaxDynamicSharedMemorySize, SM_TOT);

    // ---- transposes + tf32 convert ----
    transpose_tf32_kernel<<<dim3(64, 64), 256>>>(hs, hsT,   HIDN, Sq,   0);
    transpose_tf32_kernel<<<dim3(64, 64), 256>>>(Wq, wqkvT, HIDN, NQKV, 0);
    transpose_tf32_kernel<<<dim3(64, 32), 256>>>(Wk, wqkvT, HIDN, NQKV, NQ);
    transpose_tf32_kernel<<<dim3(64, 32), 256>>>(Wv, wqkvT, HIDN, NQKV, NQ + NKV);
    transpose_tf32_kernel<<<dim3(64, 64), 256>>>(Wo, woT,   NQ,   HIDN, 0);

    // ---- fused QKV projection (v also emitted as tf32) ----
    mma_gemm<true><<<dim3(NQKV / 128, Sq / 128), 256, GEMM_SMEM>>>(
        hsT, wqkvT, q, k, v, v32, Sq, NQKV, HIDN, 0);

    // ---- RMSNorm + RoPE (q -> tf32 only; k -> fp32 in place + tf32) ----
    norm_rope_kernel<false><<<Sq * NH  / 4, 128>>>(q, q32, qw, pcos, psin, NH);
    norm_rope_kernel<true> <<<Sq * NKH / 4, 128>>>(k, k32, kw, pcos, psin, NKH);

    // ---- fused attention ----
    flash_kernel<<<dim3(NH, Sq / 128), 256, SM_TOT>>>(q32, k32, v32, y);

    // ---- y -> yT, then output projection ----
    transpose_tf32_kernel<<<dim3(64, 64), 256>>>(y, yT, NQ, Sq, 0);
    mma_gemm<false><<<dim3(HIDN / 128, Sq / 128), 256, GEMM_SMEM>>>(
        yT, woT, out, nullptr, nullptr, nullptr, Sq, HIDN, NQ, HIDN);

    // ---- k_new / v_new ----
    tail_copy_kernel<<<8, 256>>>(k, v, out);
}

// round 10
// speedup vs baseline: 1.9980x; 1.0461x over previous
#include <cuda_runtime.h>
#include <cuda_bf16.h>
#include <math.h>

// Problem constants
#define Sq    2048
#define HIDN  2048
#define NH    16
#define NKH   8
#define HD    128
#define GRP   2          // NH / NKH
#define EPSV  1e-6f
#define SCALEV 0.08838834764831845f   // 128^-0.5

#define NQ (NH * HD)     // 2048
#define NKV (NKH * HD)   // 1024
#define NQKV (NQ + 2 * NKV)  // 4096

// ---------------- static device scratch (allocation-free rule) ----------------
__device__ float g_q[Sq * NQ];
__device__ float g_k[Sq * NKV];
__device__ float g_v[Sq * NKV];
__device__ float g_y[Sq * NQ];
__device__ unsigned g_hsT[HIDN * Sq];        // tf32, [k][m]
__device__ unsigned g_wqkvT[HIDN * NQKV];    // tf32, [k][n]  (Wq|Wk|Wv)
__device__ unsigned g_woT[NQ * HIDN];        // tf32, [k][n]
__device__ unsigned g_yT[NQ * Sq];           // tf32, [k][m]
__device__ unsigned g_q32[Sq * NQ];          // tf32 post norm+rope
__device__ unsigned g_k32[Sq * NKV];         // tf32 post norm+rope
__device__ unsigned g_v32[Sq * NKV];         // tf32 raw v

// ---------------- tf32 helpers ----------------
__device__ __forceinline__ unsigned f2tf32(float f) {
    unsigned u;
    asm("cvt.rna.tf32.f32 %0, %1;" : "=r"(u) : "f"(f));
    return u;
}

__device__ __forceinline__ void mma_tf32(float c[4],
                                         unsigned a0, unsigned a1, unsigned a2, unsigned a3,
                                         unsigned b0, unsigned b1)
{
    asm volatile(
        "mma.sync.aligned.m16n8k8.row.col.f32.tf32.tf32.f32 "
        "{%0,%1,%2,%3}, {%4,%5,%6,%7}, {%8,%9}, {%0,%1,%2,%3};"
        : "+f"(c[0]), "+f"(c[1]), "+f"(c[2]), "+f"(c[3])
        : "r"(a0), "r"(a1), "r"(a2), "r"(a3), "r"(b0), "r"(b1));
}

__device__ __forceinline__ void cpa16(unsigned dst, const unsigned* src) {
    asm volatile("cp.async.cg.shared.global [%0], [%1], 16;\n" :: "r"(dst), "l"(src));
}
#define CP_COMMIT() asm volatile("cp.async.commit_group;\n")
#define CP_WAIT2()  asm volatile("cp.async.wait_group 2;\n")
#define CP_WAIT1()  asm volatile("cp.async.wait_group 1;\n")

// ---------------- transpose + tf32 convert ----------------
__global__ __launch_bounds__(256)
void transpose_tf32_kernel(const float* __restrict__ in, unsigned* __restrict__ out,
                           int ldin, int ldout, int coloff)
{
    __shared__ float t[32][33];
    const int c0 = blockIdx.x * 32;
    const int r0 = blockIdx.y * 32;
    const int tx = threadIdx.x & 31;
    const int ty = threadIdx.x >> 5;   // 0..7

    #pragma unroll
    for (int i = 0; i < 32; i += 8)
        t[ty + i][tx] = in[(size_t)(r0 + ty + i) * ldin + c0 + tx];
    __syncthreads();
    #pragma unroll
    for (int i = 0; i < 32; i += 8)
        out[(size_t)(c0 + ty + i) * ldout + coloff + r0 + tx] = f2tf32(t[tx][ty + i]);
}

// ---------------- cp.async 3-stage pipelined tf32 GEMM ----------------
// 128 threads = 4 warps, each warp owns a 64x64 quadrant of the 128x128 tile.
// Cuts smem-crossbar traffic 1.5x vs the 8-warp 32x64 partition
// (per k-step per block: 128 LDS.32 vs 192 for the same 128 MMAs).
#define GP 136
#define STG_WORDS (2 * 32 * GP)
#define NSTAGE 3
#define GEMM_SMEM (NSTAGE * STG_WORDS * 4)   // 104448 bytes

__device__ __forceinline__ void gemm_issue(unsigned smA, unsigned smB,
                                           const unsigned* At, const unsigned* Bt,
                                           int ldA, int ldB, int kt,
                                           int bm, int bn, int tid)
{
    #pragma unroll
    for (int i = 0; i < 8; i++) {
        int e  = tid + i * 128;
        int kk = e >> 5;
        int mc = e & 31;
        cpa16(smA + (unsigned)(kk * GP + mc * 4) * 4,
              At + (size_t)(kt * 32 + kk) * ldA + bm + mc * 4);
        cpa16(smB + (unsigned)(kk * GP + mc * 4) * 4,
              Bt + (size_t)(kt * 32 + kk) * ldB + bn + mc * 4);
    }
}

template <bool QKV>
__global__ __launch_bounds__(128, 2)
void mma_gemm(const unsigned* __restrict__ At, const unsigned* __restrict__ Bt,
              float* __restrict__ C0, float* __restrict__ C1, float* __restrict__ C2,
              unsigned* __restrict__ Ct,   // tf32 mirror for v region (QKV only)
              int ldA, int ldB, int K, int ldc_plain)
{
    extern __shared__ unsigned sm[];
    const unsigned smbase = (unsigned)__cvta_generic_to_shared(sm);

    const int bm = blockIdx.y * 128;
    const int bn = blockIdx.x * 128;

    const int tid  = threadIdx.x;
    const int lane = tid & 31;
    const int wid  = tid >> 5;          // 0..3
    const int wm   = (wid >> 1) * 64;   // warp row origin
    const int wn   = (wid & 1) * 64;    // warp col origin
    const int gid  = lane >> 2;
    const int tig  = lane & 3;

    float acc[4][8][4];
    #pragma unroll
    for (int mt = 0; mt < 4; mt++)
        #pragma unroll
        for (int nt = 0; nt < 8; nt++)
            #pragma unroll
            for (int r = 0; r < 4; r++)
                acc[mt][nt][r] = 0.0f;

    const int NT = K / 32;

    gemm_issue(smbase, smbase + 32 * GP * 4, At, Bt, ldA, ldB, 0, bm, bn, tid);
    CP_COMMIT();
    gemm_issue(smbase + STG_WORDS * 4, smbase + (STG_WORDS + 32 * GP) * 4,
               At, Bt, ldA, ldB, 1, bm, bn, tid);
    CP_COMMIT();

    for (int kt = 0; kt < NT; kt++) {
        __syncthreads();
        if (kt + 2 < NT) {
            int st = (kt + 2) % NSTAGE;
            gemm_issue(smbase + st * STG_WORDS * 4,
                       smbase + (st * STG_WORDS + 32 * GP) * 4,
                       At, Bt, ldA, ldB, kt + 2, bm, bn, tid);
        }
        CP_COMMIT();
        CP_WAIT2();
        __syncthreads();

        const unsigned* As = sm + (kt % NSTAGE) * STG_WORDS;
        const unsigned* Bs = As + 32 * GP;

        #pragma unroll
        for (int ks = 0; ks < 32; ks += 8) {
            unsigned a[4][4];
            #pragma unroll
            for (int mt = 0; mt < 4; mt++) {
                int mrow = wm + mt * 16;
                a[mt][0] = As[(ks + tig    ) * GP + mrow + gid];
                a[mt][1] = As[(ks + tig    ) * GP + mrow + gid + 8];
                a[mt][2] = As[(ks + tig + 4) * GP + mrow + gid];
                a[mt][3] = As[(ks + tig + 4) * GP + mrow + gid + 8];
            }
            unsigned b[8][2];
            #pragma unroll
            for (int nt = 0; nt < 8; nt++) {
                int ncol = wn + nt * 8;
                b[nt][0] = Bs[(ks + tig    ) * GP + ncol + gid];
                b[nt][1] = Bs[(ks + tig + 4) * GP + ncol + gid];
            }
            #pragma unroll
            for (int mt = 0; mt < 4; mt++)
                #pragma unroll
                for (int nt = 0; nt < 8; nt++)
                    mma_tf32(acc[mt][nt],
                             a[mt][0], a[mt][1], a[mt][2], a[mt][3],
                             b[nt][0], b[nt][1]);
        }
    }

    // ---- epilogue ----
    float* C;
    int ldc, cb;
    bool isv = false;
    if (QKV) {
        if (bn < NQ)            { C = C0; ldc = NQ;  cb = bn; }
        else if (bn < NQ + NKV) { C = C1; ldc = NKV; cb = bn - NQ; }
        else                    { C = C2; ldc = NKV; cb = bn - NQ - NKV; isv = true; }
    } else {
        C = C0; ldc = ldc_plain; cb = bn;
    }

    #pragma unroll
    for (int mt = 0; mt < 4; mt++) {
        #pragma unroll
        for (int nt = 0; nt < 8; nt++) {
            int r0 = bm + wm + mt * 16 + gid;
            int c0 = cb + wn + nt * 8 + tig * 2;
            *(float2*)&C[(size_t)r0       * ldc + c0] = make_float2(acc[mt][nt][0], acc[mt][nt][1]);
            *(float2*)&C[(size_t)(r0 + 8) * ldc + c0] = make_float2(acc[mt][nt][2], acc[mt][nt][3]);
            if (QKV && isv) {
                *(uint2*)&Ct[(size_t)r0       * ldc + c0] =
                    make_uint2(f2tf32(acc[mt][nt][0]), f2tf32(acc[mt][nt][1]));
                *(uint2*)&Ct[(size_t)(r0 + 8) * ldc + c0] =
                    make_uint2(f2tf32(acc[mt][nt][2]), f2tf32(acc[mt][nt][3]));
            }
        }
    }
}

// ---------------- fused flash attention (cp.async double-buffered K/V) ----------------
#define QS_PAD 132
#define KS_PAD 132
#define VS_PAD 136
#define FKV_WORDS (64 * KS_PAD + 64 * VS_PAD)          // one K+V stage = 17152
#define SMF_Q 0
#define SMF_KV(st) (128 * QS_PAD + (st) * FKV_WORDS)   // K first, then V
#define SM_TOT ((128 * QS_PAD + 2 * FKV_WORDS) * 4)    // 204800 bytes

__device__ __forceinline__ void flash_issue_kv(unsigned smK, unsigned smV,
                                               const unsigned* k32, const unsigned* v32,
                                               int k0, int kh, int tid)
{
    #pragma unroll
    for (int i = 0; i < 8; i++) {
        int f   = tid + i * 256;
        int key = f >> 5;
        int c4  = f & 31;
        size_t goff = (size_t)(k0 + key) * NKV + kh * HD + c4 * 4;
        cpa16(smK + (unsigned)(key * KS_PAD + c4 * 4) * 4, k32 + goff);
        cpa16(smV + (unsigned)(key * VS_PAD + c4 * 4) * 4, v32 + goff);
    }
}

__global__ __launch_bounds__(256, 1)
void flash_kernel(const unsigned* __restrict__ q32,
                  const unsigned* __restrict__ k32,
                  const unsigned* __restrict__ v32,
                  float* __restrict__ y)
{
    extern __shared__ unsigned smf[];
    const unsigned smfb = (unsigned)__cvta_generic_to_shared(smf);
    unsigned* Qs = smf + SMF_Q;

    const int head = blockIdx.x;
    const int kh   = head / GRP;
    const int bq   = (gridDim.y - 1) - blockIdx.y;   // heavy blocks first

    const int tid  = threadIdx.x;
    const int lane = tid & 31;
    const int wid  = tid >> 5;
    const int gid  = lane >> 2;
    const int tig  = lane & 3;

    // ---- group 0: Q tile (4096 transfers -> 16 iters) + KV tile 0 ----
    #pragma unroll
    for (int i = 0; i < 16; i++) {
        int f   = tid + i * 256;
        int row = f >> 5;          // 0..127
        int c4  = f & 31;
        cpa16(smfb + (unsigned)(row * QS_PAD + c4 * 4) * 4,
              q32 + (size_t)(bq * 128 + row) * NQ + head * HD + c4 * 4);
    }
    flash_issue_kv(smfb + SMF_KV(0) * 4, smfb + (SMF_KV(0) + 64 * KS_PAD) * 4,
                   k32, v32, 0, kh, tid);
    CP_COMMIT();

    float Oa[16][4];
    #pragma unroll
    for (int nt = 0; nt < 16; nt++)
        #pragma unroll
        for (int r = 0; r < 4; r++)
            Oa[nt][r] = 0.0f;
    float mrow0 = -1e30f, mrow1 = -1e30f;
    float lrow0 = 0.0f,   lrow1 = 0.0f;

    const int i0 = bq * 128 + wid * 16 + gid;
    const int nkb = 2 * (bq + 1);

    for (int kb = 0; kb < nkb; kb++) {
        const int k0 = kb * 64;

        if (kb + 1 < nkb) {
            int st = (kb + 1) & 1;
            flash_issue_kv(smfb + SMF_KV(st) * 4,
                           smfb + (SMF_KV(st) + 64 * KS_PAD) * 4,
                           k32, v32, k0 + 64, kh, tid);
        }
        CP_COMMIT();
        CP_WAIT1();
        __syncthreads();

        const unsigned* Ks = smf + SMF_KV(kb & 1);
        const unsigned* Vs = Ks + 64 * KS_PAD;

        // ---- S = Q @ K^T ----
        float s[8][4];
        #pragma unroll
        for (int nt = 0; nt < 8; nt++)
            #pragma unroll
            for (int r = 0; r < 4; r++)
                s[nt][r] = 0.0f;

        #pragma unroll
        for (int ks = 0; ks < 128; ks += 8) {
            unsigned a0 = Qs[(wid * 16 + gid    ) * QS_PAD + ks + tig];
            unsigned a1 = Qs[(wid * 16 + gid + 8) * QS_PAD + ks + tig];
            unsigned a2 = Qs[(wid * 16 + gid    ) * QS_PAD + ks + tig + 4];
            unsigned a3 = Qs[(wid * 16 + gid + 8) * QS_PAD + ks + tig + 4];
            #pragma unroll
            for (int nt = 0; nt < 8; nt++) {
                unsigned b0 = Ks[(nt * 8 + gid) * KS_PAD + ks + tig];
                unsigned b1 = Ks[(nt * 8 + gid) * KS_PAD + ks + tig + 4];
                mma_tf32(s[nt], a0, a1, a2, a3, b0, b1);
            }
        }

        // ---- scale + causal mask ----
        const bool diag = (k0 + 64 > bq * 128);
        #pragma unroll
        for (int nt = 0; nt < 8; nt++) {
            int j = k0 + nt * 8 + tig * 2;
            #pragma unroll
            for (int r = 0; r < 4; r++) {
                int jj = j + (r & 1);
                int ii = i0 + ((r >> 1) << 3);
                float val = s[nt][r] * SCALEV;
                if (diag && jj > ii) val = -1e30f;
                s[nt][r] = val;
            }
        }

        // ---- online softmax ----
        float mx0 = -1e30f, mx1 = -1e30f;
        #pragma unroll
        for (int nt = 0; nt < 8; nt++) {
            mx0 = fmaxf(mx0, fmaxf(s[nt][0], s[nt][1]));
            mx1 = fmaxf(mx1, fmaxf(s[nt][2], s[nt][3]));
        }
        mx0 = fmaxf(mx0, __shfl_xor_sync(0xffffffffu, mx0, 1));
        mx0 = fmaxf(mx0, __shfl_xor_sync(0xffffffffu, mx0, 2));
        mx1 = fmaxf(mx1, __shfl_xor_sync(0xffffffffu, mx1, 1));
        mx1 = fmaxf(mx1, __shfl_xor_sync(0xffffffffu, mx1, 2));

        float mnew0 = fmaxf(mrow0, mx0);
        float mnew1 = fmaxf(mrow1, mx1);
        float corr0 = __expf(mrow0 - mnew0);
        float corr1 = __expf(mrow1 - mnew1);
        mrow0 = mnew0; mrow1 = mnew1;

        float sum0 = 0.0f, sum1 = 0.0f;
        #pragma unroll
        for (int nt = 0; nt < 8; nt++) {
            s[nt][0] = __expf(s[nt][0] - mnew0);
            s[nt][1] = __expf(s[nt][1] - mnew0);
            s[nt][2] = __expf(s[nt][2] - mnew1);
            s[nt][3] = __expf(s[nt][3] - mnew1);
            sum0 += s[nt][0] + s[nt][1];
            sum1 += s[nt][2] + s[nt][3];
        }
        sum0 += __shfl_xor_sync(0xffffffffu, sum0, 1);
        sum0 += __shfl_xor_sync(0xffffffffu, sum0, 2);
        sum1 += __shfl_xor_sync(0xffffffffu, sum1, 1);
        sum1 += __shfl_xor_sync(0xffffffffu, sum1, 2);
        lrow0 = lrow0 * corr0 + sum0;
        lrow1 = lrow1 * corr1 + sum1;

        #pragma unroll
        for (int nt = 0; nt < 16; nt++) {
            Oa[nt][0] *= corr0;  Oa[nt][1] *= corr0;
            Oa[nt][2] *= corr1;  Oa[nt][3] *= corr1;
        }

        // ---- O += P @ V ----
        const int srcA = (lane & ~3) | (tig >> 1);
        const int srcB = srcA + 2;
        const bool odd = (tig & 1);
        #pragma unroll
        for (int ks8 = 0; ks8 < 8; ks8++) {
            unsigned p0 = f2tf32(s[ks8][0]);
            unsigned p1 = f2tf32(s[ks8][1]);
            unsigned p2 = f2tf32(s[ks8][2]);
            unsigned p3 = f2tf32(s[ks8][3]);
            unsigned x0 = __shfl_sync(0xffffffffu, p0, srcA);
            unsigned x1 = __shfl_sync(0xffffffffu, p1, srcA);
            unsigned x2 = __shfl_sync(0xffffffffu, p2, srcA);
            unsigned x3 = __shfl_sync(0xffffffffu, p3, srcA);
            unsigned y0 = __shfl_sync(0xffffffffu, p0, srcB);
            unsigned y1 = __shfl_sync(0xffffffffu, p1, srcB);
            unsigned y2 = __shfl_sync(0xffffffffu, p2, srcB);
            unsigned y3 = __shfl_sync(0xffffffffu, p3, srcB);
            unsigned a0 = odd ? x1 : x0;
            unsigned a1 = odd ? x3 : x2;
            unsigned a2 = odd ? y1 : y0;
            unsigned a3 = odd ? y3 : y2;
            #pragma unroll
            for (int nt = 0; nt < 16; nt++) {
                unsigned b0 = Vs[(ks8 * 8 + tig    ) * VS_PAD + nt * 8 + gid];
                unsigned b1 = Vs[(ks8 * 8 + tig + 4) * VS_PAD + nt * 8 + gid];
                mma_tf32(Oa[nt], a0, a1, a2, a3, b0, b1);
            }
        }
        __syncthreads();   // all warps done with stage (kb&1) before it is re-issued
    }

    float inv0 = 1.0f / lrow0;
    float inv1 = 1.0f / lrow1;
    #pragma unroll
    for (int nt = 0; nt < 16; nt++) {
        int c0 = head * HD + nt * 8 + tig * 2;
        *(float2*)&y[(size_t)i0       * NQ + c0] = make_float2(Oa[nt][0] * inv0, Oa[nt][1] * inv0);
        *(float2*)&y[(size_t)(i0 + 8) * NQ + c0] = make_float2(Oa[nt][2] * inv1, Oa[nt][3] * inv1);
    }
}

// ---------------- RMSNorm + RoPE -> tf32 (optionally keep fp32 in place) ----------------
template <bool KEEP_F32>
__global__ __launch_bounds__(128)
void norm_rope_kernel(float* __restrict__ x, unsigned* __restrict__ xt,
                      const float* __restrict__ w,
                      const float* __restrict__ pcos,
                      const float* __restrict__ psin,
                      int nh)
{
    const int idx  = blockIdx.x * 4 + (threadIdx.x >> 5);
    const int lane = threadIdx.x & 31;
    const int s    = idx / nh;

    float* row = x + (size_t)idx * HD;
    float4 val = *(float4*)&row[lane * 4];

    float ssq = val.x * val.x + val.y * val.y + val.z * val.z + val.w * val.w;
    #pragma unroll
    for (int off = 16; off > 0; off >>= 1)
        ssq += __shfl_xor_sync(0xffffffffu, ssq, off);

    float r = rsqrtf(ssq * (1.0f / HD) + EPSV);
    float4 wv = *(const float4*)&w[lane * 4];
    float4 xn = make_float4(val.x * r * wv.x, val.y * r * wv.y,
                            val.z * r * wv.z, val.w * r * wv.w);

    float px = __shfl_xor_sync(0xffffffffu, xn.x, 16);
    float py = __shfl_xor_sync(0xffffffffu, xn.y, 16);
    float pz = __shfl_xor_sync(0xffffffffu, xn.z, 16);
    float pw = __shfl_xor_sync(0xffffffffu, xn.w, 16);

    const int cidx = (lane & 15) * 4;
    float4 cv = *(const float4*)&pcos[s * 64 + cidx];
    float4 sv = *(const float4*)&psin[s * 64 + cidx];

    float4 o;
    if (lane < 16) {
        o = make_float4(xn.x * cv.x - px * sv.x, xn.y * cv.y - py * sv.y,
                        xn.z * cv.z - pz * sv.z, xn.w * cv.w - pw * sv.w);
    } else {
        o = make_float4(px * sv.x + xn.x * cv.x, py * sv.y + xn.y * cv.y,
                        pz * sv.z + xn.z * cv.z, pw * sv.w + xn.w * cv.w);
    }
    if (KEEP_F32)
        *(float4*)&row[lane * 4] = o;
    *(uint4*)&xt[(size_t)idx * HD + lane * 4] =
        make_uint4(f2tf32(o.x), f2tf32(o.y), f2tf32(o.z), f2tf32(o.w));
}

// ---------------- k_new / v_new tail copy ----------------
__global__ void tail_copy_kernel(const float* __restrict__ k,
                                 const float* __restrict__ v,
                                 float* __restrict__ out)
{
    int t = blockIdx.x * blockDim.x + threadIdx.x;
    const size_t base = (size_t)Sq * HIDN;
    if (t < NKV)
        out[base + t] = k[(size_t)(Sq - 1) * NKV + t];
    else
        out[base + t] = v[(size_t)(Sq - 1) * NKV + (t - NKV)];
}

// ---------------- launcher ----------------
extern "C" void kernel_launch(void* const* d_in, const int* in_sizes, int n_in,
                              void* d_out, int out_size)
{
    const float* hs   = (const float*)d_in[0];
    const float* pcos = (const float*)d_in[1];
    const float* psin = (const float*)d_in[2];
    // d_in[3] = atten_mask (causal, reproduced arithmetically)
    const float* Wq   = (const float*)d_in[4];
    const float* Wk   = (const float*)d_in[5];
    const float* Wv   = (const float*)d_in[6];
    const float* Wo   = (const float*)d_in[7];
    const float* qw   = (const float*)d_in[8];
    const float* kw   = (const float*)d_in[9];
    float* out = (float*)d_out;

    float *q, *k, *v, *y;
    unsigned *hsT, *wqkvT, *woT, *yT, *q32, *k32, *v32;
    cudaGetSymbolAddress((void**)&q,     g_q);
    cudaGetSymbolAddress((void**)&k,     g_k);
    cudaGetSymbolAddress((void**)&v,     g_v);
    cudaGetSymbolAddress((void**)&y,     g_y);
    cudaGetSymbolAddress((void**)&hsT,   g_hsT);
    cudaGetSymbolAddress((void**)&wqkvT, g_wqkvT);
    cudaGetSymbolAddress((void**)&woT,   g_woT);
    cudaGetSymbolAddress((void**)&yT,    g_yT);
    cudaGetSymbolAddress((void**)&q32,   g_q32);
    cudaGetSymbolAddress((void**)&k32,   g_k32);
    cudaGetSymbolAddress((void**)&v32,   g_v32);

    cudaFuncSetAttribute(mma_gemm<true>,
                         cudaFuncAttributeMaxDynamicSharedMemorySize, GEMM_SMEM);
    cudaFuncSetAttribute(mma_gemm<false>,
                         cudaFuncAttributeMaxDynamicSharedMemorySize, GEMM_SMEM);
    cudaFuncSetAttribute(flash_kernel,
                         cudaFuncAttributeMaxDynamicSharedMemorySize, SM_TOT);

    // ---- transposes + tf32 convert ----
    transpose_tf32_kernel<<<dim3(64, 64), 256>>>(hs, hsT,   HIDN, Sq,   0);
    transpose_tf32_kernel<<<dim3(64, 64), 256>>>(Wq, wqkvT, HIDN, NQKV, 0);
    transpose_tf32_kernel<<<dim3(64, 32), 256>>>(Wk, wqkvT, HIDN, NQKV, NQ);
    transpose_tf32_kernel<<<dim3(64, 32), 256>>>(Wv, wqkvT, HIDN, NQKV, NQ + NKV);
    transpose_tf32_kernel<<<dim3(64, 64), 256>>>(Wo, woT,   NQ,   HIDN, 0);

    // ---- fused QKV projection (v also emitted as tf32) ----
    mma_gemm<true><<<dim3(NQKV / 128, Sq / 128), 128, GEMM_SMEM>>>(
        hsT, wqkvT, q, k, v, v32, Sq, NQKV, HIDN, 0);

    // ---- RMSNorm + RoPE (q -> tf32 only; k -> fp32 in place + tf32) ----
    norm_rope_kernel<false><<<Sq * NH  / 4, 128>>>(q, q32, qw, pcos, psin, NH);
    norm_rope_kernel<true> <<<Sq * NKH / 4, 128>>>(k, k32, kw, pcos, psin, NKH);

    // ---- fused attention ----
    flash_kernel<<<dim3(NH, Sq / 128), 256, SM_TOT>>>(q32, k32, v32, y);

    // ---- y -> yT, then output projection ----
    transpose_tf32_kernel<<<dim3(64, 64), 256>>>(y, yT, NQ, Sq, 0);
    mma_gemm<false><<<dim3(HIDN / 128, Sq / 128), 128, GEMM_SMEM>>>(
        yT, woT, out, nullptr, nullptr, nullptr, Sq, HIDN, NQ, HIDN);

    // ---- k_new / v_new ----
    tail_copy_kernel<<<8, 256>>>(k, v, out);
}